// round 6
// baseline (speedup 1.0000x reference)
#include <cuda_runtime.h>
#include <cuda_bf16.h>
#include <cstdint>

// ---------------- problem constants ----------------
#define N_NODES 50000
#define N_EDGES 800000
#define IN_C    128
#define HID_C   16
#define HEADS   8
#define H1      (HEADS * HID_C)   // 128
#define OUT_C   64
#define NEG_SLOPE 0.2f

// ---------------- scratch (device globals; no allocation allowed) ----------------
__device__ float g_xh1[(size_t)N_NODES * H1];     // layer1 linear output  [N,128]
__device__ float g_asrc1[(size_t)N_NODES * HEADS];
__device__ float g_adst1[(size_t)N_NODES * HEADS];
__device__ float g_denom1[(size_t)N_NODES * HEADS];
__device__ float g_acc1[(size_t)N_NODES * H1];    // layer1 aggregation + h (after ELU)
__device__ float g_xh2[(size_t)N_NODES * OUT_C];  // layer2 linear output  [N,64]
__device__ float g_asrc2[N_NODES];
__device__ float g_adst2[N_NODES];
__device__ float g_denom2[N_NODES];
__device__ int   g_src[N_EDGES];
__device__ int   g_dst[N_EDGES];
__device__ int   g_is64;

// ---------------- helpers ----------------
__device__ __forceinline__ float lrelu(float x) { return x > 0.f ? x : NEG_SLOPE * x; }

// ---------------- edge dtype detection + canonicalization ----------------
// int64 data (values < 50000, little-endian) => odd 32-bit slots are all zero.
// int32 data => odd slots are random node indices (never all zero over 64K).
__global__ void detect_kernel(const unsigned int* __restrict__ ei32) {
    __shared__ unsigned int sv[256];
    int tid = threadIdx.x;
    unsigned int v = 0;
    for (int i = tid; i < 65536; i += 256) v |= ei32[2 * i + 1];
    sv[tid] = v;
    __syncthreads();
    for (int s = 128; s > 0; s >>= 1) {
        if (tid < s) sv[tid] |= sv[tid + s];
        __syncthreads();
    }
    if (tid == 0) g_is64 = (sv[0] == 0u) ? 1 : 0;
}

__global__ void convert_kernel(const int* __restrict__ ei) {
    int e = blockIdx.x * blockDim.x + threadIdx.x;
    if (e >= N_EDGES) return;
    int s, d;
    if (g_is64) {
        const long long* p = (const long long*)ei;
        s = (int)p[e];
        d = (int)p[N_EDGES + e];
    } else {
        s = ei[e];
        d = ei[e + N_EDGES];
    }
    g_src[e] = s;
    g_dst[e] = d;
}

// ---------------- zero kernels ----------------
__global__ void zero_acc1_kernel() {
    int gid = blockIdx.x * blockDim.x + threadIdx.x;
    if (gid < N_NODES * (H1 / 4)) {
        reinterpret_cast<float4*>(g_acc1)[gid] = make_float4(0.f, 0.f, 0.f, 0.f);
    }
}
__global__ void zero_out_kernel(float* __restrict__ out) {
    int gid = blockIdx.x * blockDim.x + threadIdx.x;
    if (gid < N_NODES * (OUT_C / 4)) {
        reinterpret_cast<float4*>(out)[gid] = make_float4(0.f, 0.f, 0.f, 0.f);
    }
}

// ---------------- tiled GEMM: C[M,N] = A[M,128] * B[128,N] ----------------
template <int N, int TN>
__global__ void gemm_kernel(const float* __restrict__ A, const float* __restrict__ B,
                            float* __restrict__ C, int M) {
    constexpr int K  = 128;
    constexpr int BM = 64;
    constexpr int BK = 16;
    __shared__ float As[BK][BM + 4];
    __shared__ float Bs[BK][N];

    int tid = threadIdx.x;
    int tx = tid & 15;
    int ty = tid >> 4;
    int m0 = blockIdx.x * BM;

    float acc[4][TN];
#pragma unroll
    for (int r = 0; r < 4; r++)
#pragma unroll
        for (int c = 0; c < TN; c++) acc[r][c] = 0.f;

    int arow = tid >> 2;
    int akk  = (tid & 3) * 4;

    for (int kt = 0; kt < K; kt += BK) {
        float4 a4 = make_float4(0.f, 0.f, 0.f, 0.f);
        int gr = m0 + arow;
        if (gr < M)
            a4 = *reinterpret_cast<const float4*>(A + (size_t)gr * K + kt + akk);
        As[akk + 0][arow] = a4.x;
        As[akk + 1][arow] = a4.y;
        As[akk + 2][arow] = a4.z;
        As[akk + 3][arow] = a4.w;

        constexpr int NF4 = BK * N / 4;
#pragma unroll
        for (int i = 0; i < NF4 / 256; i++) {
            int idx = tid + i * 256;
            int br = idx / (N / 4);
            int bc = idx % (N / 4);
            float4 b4 = *reinterpret_cast<const float4*>(B + (size_t)(kt + br) * N + bc * 4);
            *reinterpret_cast<float4*>(&Bs[br][bc * 4]) = b4;
        }
        __syncthreads();

#pragma unroll
        for (int k = 0; k < BK; k++) {
            float a[4];
#pragma unroll
            for (int r = 0; r < 4; r++) a[r] = As[k][ty * 4 + r];
            float b[TN];
#pragma unroll
            for (int c = 0; c < TN; c++) b[c] = Bs[k][tx * TN + c];
#pragma unroll
            for (int r = 0; r < 4; r++)
#pragma unroll
                for (int c = 0; c < TN; c++) acc[r][c] += a[r] * b[c];
        }
        __syncthreads();
    }

#pragma unroll
    for (int r = 0; r < 4; r++) {
        int gr = m0 + ty * 4 + r;
        if (gr < M) {
#pragma unroll
            for (int c = 0; c < TN; c += 4) {
                float4 v = make_float4(acc[r][c], acc[r][c + 1], acc[r][c + 2], acc[r][c + 3]);
                *reinterpret_cast<float4*>(C + (size_t)gr * N + tx * TN + c) = v;
            }
        }
    }
}

// ---------------- layer 1 attention coefficients (warp per node) ----------------
__global__ void attn1_kernel(const float* __restrict__ att_src,
                             const float* __restrict__ att_dst) {
    int gw   = (blockIdx.x * blockDim.x + threadIdx.x) >> 5;
    int lane = threadIdx.x & 31;
    if (gw >= N_NODES) return;
    float4 xv = *reinterpret_cast<const float4*>(g_xh1 + (size_t)gw * H1 + lane * 4);
    float4 as = *reinterpret_cast<const float4*>(att_src + lane * 4);
    float4 ad = *reinterpret_cast<const float4*>(att_dst + lane * 4);
    float ps = xv.x * as.x + xv.y * as.y + xv.z * as.z + xv.w * as.w;
    float pd = xv.x * ad.x + xv.y * ad.y + xv.z * ad.z + xv.w * ad.w;
    ps += __shfl_xor_sync(0xffffffffu, ps, 1);
    ps += __shfl_xor_sync(0xffffffffu, ps, 2);
    pd += __shfl_xor_sync(0xffffffffu, pd, 1);
    pd += __shfl_xor_sync(0xffffffffu, pd, 2);
    if ((lane & 3) == 0) {
        int h = lane >> 2;
        g_asrc1[(size_t)gw * HEADS + h] = ps;
        g_adst1[(size_t)gw * HEADS + h] = pd;
        g_denom1[(size_t)gw * HEADS + h] = __expf(lrelu(ps + pd));  // self-loop seed
    }
}

// ---------------- layer 1 edge pass A: softmax denominators ----------------
__global__ void edge1_denom_kernel() {
    int e = blockIdx.x * blockDim.x + threadIdx.x;
    if (e >= N_EDGES) return;
    int s = g_src[e], d = g_dst[e];
    const float4* ap = reinterpret_cast<const float4*>(g_asrc1 + (size_t)s * HEADS);
    const float4* bp = reinterpret_cast<const float4*>(g_adst1 + (size_t)d * HEADS);
    float4 a0 = __ldg(ap), a1 = __ldg(ap + 1);
    float4 b0 = __ldg(bp), b1 = __ldg(bp + 1);
    float4 e0 = make_float4(__expf(lrelu(a0.x + b0.x)), __expf(lrelu(a0.y + b0.y)),
                            __expf(lrelu(a0.z + b0.z)), __expf(lrelu(a0.w + b0.w)));
    float4 e1 = make_float4(__expf(lrelu(a1.x + b1.x)), __expf(lrelu(a1.y + b1.y)),
                            __expf(lrelu(a1.z + b1.z)), __expf(lrelu(a1.w + b1.w)));
    atomicAdd(reinterpret_cast<float4*>(g_denom1 + (size_t)d * HEADS), e0);
    atomicAdd(reinterpret_cast<float4*>(g_denom1 + (size_t)d * HEADS + 4), e1);
}

// ---------------- layer 1 edge pass B: weighted aggregation (warp per edge) ----------------
__global__ void edge1_aggregate_kernel() {
    int gw   = (blockIdx.x * blockDim.x + threadIdx.x) >> 5;
    int lane = threadIdx.x & 31;
    if (gw >= N_EDGES) return;
    int s = g_src[gw], d = g_dst[gw];
    int h = lane >> 2;
    float as = __ldg(g_asrc1 + (size_t)s * HEADS + h);
    float ad = __ldg(g_adst1 + (size_t)d * HEADS + h);
    float dn = __ldg(g_denom1 + (size_t)d * HEADS + h);
    float alpha = __expf(lrelu(as + ad)) / (dn + 1e-16f);
    float4 xv = *reinterpret_cast<const float4*>(g_xh1 + (size_t)s * H1 + lane * 4);
    float4 msg = make_float4(xv.x * alpha, xv.y * alpha, xv.z * alpha, xv.w * alpha);
    atomicAdd(reinterpret_cast<float4*>(g_acc1 + (size_t)d * H1 + lane * 4), msg);
}

// ---------------- layer 1 finalize: self-loop msg + bias + ELU ----------------
__global__ void fin1_kernel(const float* __restrict__ b1) {
    int gid = blockIdx.x * blockDim.x + threadIdx.x;
    if (gid >= N_NODES * 32) return;
    int i  = gid >> 5;
    int c4 = gid & 31;
    int h  = c4 >> 2;
    float as = g_asrc1[(size_t)i * HEADS + h];
    float ad = g_adst1[(size_t)i * HEADS + h];
    float al = __expf(lrelu(as + ad)) / (g_denom1[(size_t)i * HEADS + h] + 1e-16f);
    float4 acc = *reinterpret_cast<const float4*>(g_acc1 + (size_t)i * H1 + c4 * 4);
    float4 xv  = *reinterpret_cast<const float4*>(g_xh1 + (size_t)i * H1 + c4 * 4);
    float4 bb  = *reinterpret_cast<const float4*>(b1 + c4 * 4);
    float v;
    v = acc.x + xv.x * al + bb.x; acc.x = v > 0.f ? v : expm1f(v);
    v = acc.y + xv.y * al + bb.y; acc.y = v > 0.f ? v : expm1f(v);
    v = acc.z + xv.z * al + bb.z; acc.z = v > 0.f ? v : expm1f(v);
    v = acc.w + xv.w * al + bb.w; acc.w = v > 0.f ? v : expm1f(v);
    *reinterpret_cast<float4*>(g_acc1 + (size_t)i * H1 + c4 * 4) = acc;
}

// ---------------- layer 2 attention coefficients (warp per node) ----------------
__global__ void attn2_kernel(const float* __restrict__ att_src,
                             const float* __restrict__ att_dst) {
    int gw   = (blockIdx.x * blockDim.x + threadIdx.x) >> 5;
    int lane = threadIdx.x & 31;
    if (gw >= N_NODES) return;
    float2 xv = *reinterpret_cast<const float2*>(g_xh2 + (size_t)gw * OUT_C + lane * 2);
    float2 as = *reinterpret_cast<const float2*>(att_src + lane * 2);
    float2 ad = *reinterpret_cast<const float2*>(att_dst + lane * 2);
    float ps = xv.x * as.x + xv.y * as.y;
    float pd = xv.x * ad.x + xv.y * ad.y;
#pragma unroll
    for (int m = 16; m > 0; m >>= 1) {
        ps += __shfl_xor_sync(0xffffffffu, ps, m);
        pd += __shfl_xor_sync(0xffffffffu, pd, m);
    }
    if (lane == 0) {
        g_asrc2[gw] = ps;
        g_adst2[gw] = pd;
        g_denom2[gw] = __expf(lrelu(ps + pd));   // self-loop seed
    }
}

// ---------------- layer 2 edge pass A ----------------
__global__ void edge2_denom_kernel() {
    int e = blockIdx.x * blockDim.x + threadIdx.x;
    if (e >= N_EDGES) return;
    int s = g_src[e], d = g_dst[e];
    float t = __expf(lrelu(__ldg(g_asrc2 + s) + __ldg(g_adst2 + d)));
    atomicAdd(g_denom2 + d, t);
}

// ---------------- layer 2 edge pass B (warp per edge) ----------------
__global__ void edge2_aggregate_kernel(float* __restrict__ out) {
    int gw   = (blockIdx.x * blockDim.x + threadIdx.x) >> 5;
    int lane = threadIdx.x & 31;
    if (gw >= N_EDGES) return;
    int s = g_src[gw], d = g_dst[gw];
    float as = __ldg(g_asrc2 + s);
    float ad = __ldg(g_adst2 + d);
    float dn = __ldg(g_denom2 + d);
    float alpha = __expf(lrelu(as + ad)) / (dn + 1e-16f);
    float2 xv = *reinterpret_cast<const float2*>(g_xh2 + (size_t)s * OUT_C + lane * 2);
    float2 msg = make_float2(xv.x * alpha, xv.y * alpha);
    atomicAdd(reinterpret_cast<float2*>(out + (size_t)d * OUT_C + lane * 2), msg);
}

// ---------------- layer 2 finalize: self-loop msg + bias ----------------
__global__ void fin2_kernel(const float* __restrict__ b2, float* __restrict__ out) {
    int gid = blockIdx.x * blockDim.x + threadIdx.x;
    if (gid >= N_NODES * 16) return;
    int i = gid >> 4;
    int c = gid & 15;
    float al = __expf(lrelu(g_asrc2[i] + g_adst2[i])) / (g_denom2[i] + 1e-16f);
    float4 o  = *reinterpret_cast<const float4*>(out + (size_t)i * OUT_C + c * 4);
    float4 xv = *reinterpret_cast<const float4*>(g_xh2 + (size_t)i * OUT_C + c * 4);
    float4 bb = *reinterpret_cast<const float4*>(b2 + c * 4);
    o.x += xv.x * al + bb.x;
    o.y += xv.y * al + bb.y;
    o.z += xv.z * al + bb.z;
    o.w += xv.w * al + bb.w;
    *reinterpret_cast<float4*>(out + (size_t)i * OUT_C + c * 4) = o;
}

// ---------------- launch ----------------
extern "C" void kernel_launch(void* const* d_in, const int* in_sizes, int n_in,
                              void* d_out, int out_size) {
    const float* x        = (const float*)d_in[0];
    const int*   ei       = (const int*)d_in[1];
    const float* W1       = (const float*)d_in[2];
    const float* att_src1 = (const float*)d_in[3];
    const float* att_dst1 = (const float*)d_in[4];
    const float* b1       = (const float*)d_in[5];
    const float* W2       = (const float*)d_in[6];
    const float* att_src2 = (const float*)d_in[7];
    const float* att_dst2 = (const float*)d_in[8];
    const float* b2       = (const float*)d_in[9];
    float*       out      = (float*)d_out;

    // CRITICAL: get true DEVICE addresses of the __device__ scratch symbols.
    // Passing the symbol name from host code passes the host shadow address,
    // which GB300's ATS happily (and silently) dereferences into host memory.
    void *p_xh1 = nullptr, *p_acc1 = nullptr, *p_xh2 = nullptr;
    cudaGetSymbolAddress(&p_xh1,  g_xh1);
    cudaGetSymbolAddress(&p_acc1, g_acc1);
    cudaGetSymbolAddress(&p_xh2,  g_xh2);
    float* xh1  = (float*)p_xh1;
    float* acc1 = (float*)p_acc1;
    float* xh2  = (float*)p_xh2;

    const int T = 256;
    const int gemm_blocks  = (N_NODES + 63) / 64;
    const int node_warps   = (N_NODES * 32 + T - 1) / T;
    const int edge_threads = (N_EDGES + T - 1) / T;
    const int edge_warps   = (N_EDGES * 32 + T - 1) / T;

    // ---- canonicalize edge indices (dtype-agnostic) ----
    detect_kernel<<<1, T>>>((const unsigned int*)ei);
    convert_kernel<<<edge_threads, T>>>(ei);

    // ---- layer 1 ----
    zero_acc1_kernel<<<(N_NODES * 32 + T - 1) / T, T>>>();
    gemm_kernel<128, 8><<<gemm_blocks, T>>>(x, W1, xh1, N_NODES);
    attn1_kernel<<<node_warps, T>>>(att_src1, att_dst1);
    edge1_denom_kernel<<<edge_threads, T>>>();
    edge1_aggregate_kernel<<<edge_warps, T>>>();
    fin1_kernel<<<node_warps, T>>>(b1);

    // ---- layer 2 ----
    gemm_kernel<64, 4><<<gemm_blocks, T>>>(acc1, W2, xh2, N_NODES);
    attn2_kernel<<<node_warps, T>>>(att_src2, att_dst2);
    zero_out_kernel<<<(N_NODES * 16 + T - 1) / T, T>>>(out);
    edge2_denom_kernel<<<edge_threads, T>>>();
    edge2_aggregate_kernel<<<edge_warps, T>>>(out);
    fin2_kernel<<<(N_NODES * 16 + T - 1) / T, T>>>(b2, out);
}

// round 7
// speedup vs baseline: 1.0015x; 1.0015x over previous
#include <cuda_runtime.h>
#include <cuda_bf16.h>
#include <cstdint>

// ---------------- problem constants ----------------
#define N_NODES 50000
#define N_EDGES 800000
#define IN_C    128
#define HID_C   16
#define HEADS   8
#define H1      (HEADS * HID_C)   // 128
#define OUT_C   64
#define NEG_SLOPE 0.2f

// ---------------- scratch (device globals; no allocation allowed) ----------------
__device__ float g_xh1[(size_t)N_NODES * H1];     // layer1 linear output  [N,128]
__device__ float g_asrc1[(size_t)N_NODES * HEADS];
__device__ float g_adst1[(size_t)N_NODES * HEADS];
__device__ float g_denom1[(size_t)N_NODES * HEADS];
__device__ float g_acc1[(size_t)N_NODES * H1];    // layer1 aggregation + h (after ELU)
__device__ float g_xh2[(size_t)N_NODES * OUT_C];  // layer2 linear output  [N,64]
__device__ float g_asrc2[N_NODES];
__device__ float g_adst2[N_NODES];
__device__ float g_denom2[N_NODES];
__device__ int   g_src[N_EDGES];
__device__ int   g_dst[N_EDGES];
__device__ int   g_is64;

// ---------------- helpers ----------------
__device__ __forceinline__ float lrelu(float x) { return x > 0.f ? x : NEG_SLOPE * x; }

// ---------------- edge dtype detection + canonicalization ----------------
// int64 data (values < 50000, little-endian) => odd 32-bit slots are all zero.
// int32 data => odd slots are random node indices (never all zero over 64K).
__global__ void detect_kernel(const unsigned int* __restrict__ ei32) {
    __shared__ unsigned int sv[256];
    int tid = threadIdx.x;
    unsigned int v = 0;
    for (int i = tid; i < 65536; i += 256) v |= ei32[2 * i + 1];
    sv[tid] = v;
    __syncthreads();
    for (int s = 128; s > 0; s >>= 1) {
        if (tid < s) sv[tid] |= sv[tid + s];
        __syncthreads();
    }
    if (tid == 0) g_is64 = (sv[0] == 0u) ? 1 : 0;
}

__global__ void convert_kernel(const int* __restrict__ ei) {
    int e = blockIdx.x * blockDim.x + threadIdx.x;
    if (e >= N_EDGES) return;
    int s, d;
    if (g_is64) {
        const long long* p = (const long long*)ei;
        s = (int)p[e];
        d = (int)p[N_EDGES + e];
    } else {
        s = ei[e];
        d = ei[e + N_EDGES];
    }
    g_src[e] = s;
    g_dst[e] = d;
}

// ---------------- zero kernels ----------------
__global__ void zero_acc1_kernel() {
    int gid = blockIdx.x * blockDim.x + threadIdx.x;
    if (gid < N_NODES * (H1 / 4)) {
        reinterpret_cast<float4*>(g_acc1)[gid] = make_float4(0.f, 0.f, 0.f, 0.f);
    }
}
__global__ void zero_out_kernel(float* __restrict__ out) {
    int gid = blockIdx.x * blockDim.x + threadIdx.x;
    if (gid < N_NODES * (OUT_C / 4)) {
        reinterpret_cast<float4*>(out)[gid] = make_float4(0.f, 0.f, 0.f, 0.f);
    }
}

// ---------------- tiled GEMM: C[M,N] = A[M,128] * B[128,N] ----------------
template <int N, int TN>
__global__ void gemm_kernel(const float* __restrict__ A, const float* __restrict__ B,
                            float* __restrict__ C, int M) {
    constexpr int K  = 128;
    constexpr int BM = 64;
    constexpr int BK = 16;
    __shared__ float As[BK][BM + 4];
    __shared__ float Bs[BK][N];

    int tid = threadIdx.x;
    int tx = tid & 15;
    int ty = tid >> 4;
    int m0 = blockIdx.x * BM;

    float acc[4][TN];
#pragma unroll
    for (int r = 0; r < 4; r++)
#pragma unroll
        for (int c = 0; c < TN; c++) acc[r][c] = 0.f;

    int arow = tid >> 2;
    int akk  = (tid & 3) * 4;

    for (int kt = 0; kt < K; kt += BK) {
        float4 a4 = make_float4(0.f, 0.f, 0.f, 0.f);
        int gr = m0 + arow;
        if (gr < M)
            a4 = *reinterpret_cast<const float4*>(A + (size_t)gr * K + kt + akk);
        As[akk + 0][arow] = a4.x;
        As[akk + 1][arow] = a4.y;
        As[akk + 2][arow] = a4.z;
        As[akk + 3][arow] = a4.w;

        constexpr int NF4 = BK * N / 4;
#pragma unroll
        for (int i = 0; i < NF4 / 256; i++) {
            int idx = tid + i * 256;
            int br = idx / (N / 4);
            int bc = idx % (N / 4);
            float4 b4 = *reinterpret_cast<const float4*>(B + (size_t)(kt + br) * N + bc * 4);
            *reinterpret_cast<float4*>(&Bs[br][bc * 4]) = b4;
        }
        __syncthreads();

#pragma unroll
        for (int k = 0; k < BK; k++) {
            float a[4];
#pragma unroll
            for (int r = 0; r < 4; r++) a[r] = As[k][ty * 4 + r];
            float b[TN];
#pragma unroll
            for (int c = 0; c < TN; c++) b[c] = Bs[k][tx * TN + c];
#pragma unroll
            for (int r = 0; r < 4; r++)
#pragma unroll
                for (int c = 0; c < TN; c++) acc[r][c] += a[r] * b[c];
        }
        __syncthreads();
    }

#pragma unroll
    for (int r = 0; r < 4; r++) {
        int gr = m0 + ty * 4 + r;
        if (gr < M) {
#pragma unroll
            for (int c = 0; c < TN; c += 4) {
                float4 v = make_float4(acc[r][c], acc[r][c + 1], acc[r][c + 2], acc[r][c + 3]);
                *reinterpret_cast<float4*>(C + (size_t)gr * N + tx * TN + c) = v;
            }
        }
    }
}

// ---------------- layer 1 attention coefficients (warp per node) ----------------
__global__ void attn1_kernel(const float* __restrict__ att_src,
                             const float* __restrict__ att_dst) {
    int gw   = (blockIdx.x * blockDim.x + threadIdx.x) >> 5;
    int lane = threadIdx.x & 31;
    if (gw >= N_NODES) return;
    float4 xv = *reinterpret_cast<const float4*>(g_xh1 + (size_t)gw * H1 + lane * 4);
    float4 as = *reinterpret_cast<const float4*>(att_src + lane * 4);
    float4 ad = *reinterpret_cast<const float4*>(att_dst + lane * 4);
    float ps = xv.x * as.x + xv.y * as.y + xv.z * as.z + xv.w * as.w;
    float pd = xv.x * ad.x + xv.y * ad.y + xv.z * ad.z + xv.w * ad.w;
    ps += __shfl_xor_sync(0xffffffffu, ps, 1);
    ps += __shfl_xor_sync(0xffffffffu, ps, 2);
    pd += __shfl_xor_sync(0xffffffffu, pd, 1);
    pd += __shfl_xor_sync(0xffffffffu, pd, 2);
    if ((lane & 3) == 0) {
        int h = lane >> 2;
        g_asrc1[(size_t)gw * HEADS + h] = ps;
        g_adst1[(size_t)gw * HEADS + h] = pd;
        g_denom1[(size_t)gw * HEADS + h] = __expf(lrelu(ps + pd));  // self-loop seed
    }
}

// ---------------- layer 1 edge pass A: softmax denominators ----------------
__global__ void edge1_denom_kernel() {
    int e = blockIdx.x * blockDim.x + threadIdx.x;
    if (e >= N_EDGES) return;
    int s = g_src[e], d = g_dst[e];
    const float4* ap = reinterpret_cast<const float4*>(g_asrc1 + (size_t)s * HEADS);
    const float4* bp = reinterpret_cast<const float4*>(g_adst1 + (size_t)d * HEADS);
    float4 a0 = __ldg(ap), a1 = __ldg(ap + 1);
    float4 b0 = __ldg(bp), b1 = __ldg(bp + 1);
    float4 e0 = make_float4(__expf(lrelu(a0.x + b0.x)), __expf(lrelu(a0.y + b0.y)),
                            __expf(lrelu(a0.z + b0.z)), __expf(lrelu(a0.w + b0.w)));
    float4 e1 = make_float4(__expf(lrelu(a1.x + b1.x)), __expf(lrelu(a1.y + b1.y)),
                            __expf(lrelu(a1.z + b1.z)), __expf(lrelu(a1.w + b1.w)));
    atomicAdd(reinterpret_cast<float4*>(g_denom1 + (size_t)d * HEADS), e0);
    atomicAdd(reinterpret_cast<float4*>(g_denom1 + (size_t)d * HEADS + 4), e1);
}

// ---------------- layer 1 edge pass B: weighted aggregation (warp per edge) ----------------
__global__ void edge1_aggregate_kernel() {
    int gw   = (blockIdx.x * blockDim.x + threadIdx.x) >> 5;
    int lane = threadIdx.x & 31;
    if (gw >= N_EDGES) return;
    int s = g_src[gw], d = g_dst[gw];
    int h = lane >> 2;
    float as = __ldg(g_asrc1 + (size_t)s * HEADS + h);
    float ad = __ldg(g_adst1 + (size_t)d * HEADS + h);
    float dn = __ldg(g_denom1 + (size_t)d * HEADS + h);
    float alpha = __expf(lrelu(as + ad)) / (dn + 1e-16f);
    float4 xv = *reinterpret_cast<const float4*>(g_xh1 + (size_t)s * H1 + lane * 4);
    float4 msg = make_float4(xv.x * alpha, xv.y * alpha, xv.z * alpha, xv.w * alpha);
    atomicAdd(reinterpret_cast<float4*>(g_acc1 + (size_t)d * H1 + lane * 4), msg);
}

// ---------------- layer 1 finalize: self-loop msg + bias + ELU ----------------
__global__ void fin1_kernel(const float* __restrict__ b1) {
    int gid = blockIdx.x * blockDim.x + threadIdx.x;
    if (gid >= N_NODES * 32) return;
    int i  = gid >> 5;
    int c4 = gid & 31;
    int h  = c4 >> 2;
    float as = g_asrc1[(size_t)i * HEADS + h];
    float ad = g_adst1[(size_t)i * HEADS + h];
    float al = __expf(lrelu(as + ad)) / (g_denom1[(size_t)i * HEADS + h] + 1e-16f);
    float4 acc = *reinterpret_cast<const float4*>(g_acc1 + (size_t)i * H1 + c4 * 4);
    float4 xv  = *reinterpret_cast<const float4*>(g_xh1 + (size_t)i * H1 + c4 * 4);
    float4 bb  = *reinterpret_cast<const float4*>(b1 + c4 * 4);
    float v;
    v = acc.x + xv.x * al + bb.x; acc.x = v > 0.f ? v : expm1f(v);
    v = acc.y + xv.y * al + bb.y; acc.y = v > 0.f ? v : expm1f(v);
    v = acc.z + xv.z * al + bb.z; acc.z = v > 0.f ? v : expm1f(v);
    v = acc.w + xv.w * al + bb.w; acc.w = v > 0.f ? v : expm1f(v);
    *reinterpret_cast<float4*>(g_acc1 + (size_t)i * H1 + c4 * 4) = acc;
}

// ---------------- layer 2 attention coefficients (warp per node) ----------------
__global__ void attn2_kernel(const float* __restrict__ att_src,
                             const float* __restrict__ att_dst) {
    int gw   = (blockIdx.x * blockDim.x + threadIdx.x) >> 5;
    int lane = threadIdx.x & 31;
    if (gw >= N_NODES) return;
    float2 xv = *reinterpret_cast<const float2*>(g_xh2 + (size_t)gw * OUT_C + lane * 2);
    float2 as = *reinterpret_cast<const float2*>(att_src + lane * 2);
    float2 ad = *reinterpret_cast<const float2*>(att_dst + lane * 2);
    float ps = xv.x * as.x + xv.y * as.y;
    float pd = xv.x * ad.x + xv.y * ad.y;
#pragma unroll
    for (int m = 16; m > 0; m >>= 1) {
        ps += __shfl_xor_sync(0xffffffffu, ps, m);
        pd += __shfl_xor_sync(0xffffffffu, pd, m);
    }
    if (lane == 0) {
        g_asrc2[gw] = ps;
        g_adst2[gw] = pd;
        g_denom2[gw] = __expf(lrelu(ps + pd));   // self-loop seed
    }
}

// ---------------- layer 2 edge pass A ----------------
__global__ void edge2_denom_kernel() {
    int e = blockIdx.x * blockDim.x + threadIdx.x;
    if (e >= N_EDGES) return;
    int s = g_src[e], d = g_dst[e];
    float t = __expf(lrelu(__ldg(g_asrc2 + s) + __ldg(g_adst2 + d)));
    atomicAdd(g_denom2 + d, t);
}

// ---------------- layer 2 edge pass B (warp per edge) ----------------
__global__ void edge2_aggregate_kernel(float* __restrict__ out) {
    int gw   = (blockIdx.x * blockDim.x + threadIdx.x) >> 5;
    int lane = threadIdx.x & 31;
    if (gw >= N_EDGES) return;
    int s = g_src[gw], d = g_dst[gw];
    float as = __ldg(g_asrc2 + s);
    float ad = __ldg(g_adst2 + d);
    float dn = __ldg(g_denom2 + d);
    float alpha = __expf(lrelu(as + ad)) / (dn + 1e-16f);
    float2 xv = *reinterpret_cast<const float2*>(g_xh2 + (size_t)s * OUT_C + lane * 2);
    float2 msg = make_float2(xv.x * alpha, xv.y * alpha);
    atomicAdd(reinterpret_cast<float2*>(out + (size_t)d * OUT_C + lane * 2), msg);
}

// ---------------- layer 2 finalize: self-loop msg + bias ----------------
__global__ void fin2_kernel(const float* __restrict__ b2, float* __restrict__ out) {
    int gid = blockIdx.x * blockDim.x + threadIdx.x;
    if (gid >= N_NODES * 16) return;
    int i = gid >> 4;
    int c = gid & 15;
    float al = __expf(lrelu(g_asrc2[i] + g_adst2[i])) / (g_denom2[i] + 1e-16f);
    float4 o  = *reinterpret_cast<const float4*>(out + (size_t)i * OUT_C + c * 4);
    float4 xv = *reinterpret_cast<const float4*>(g_xh2 + (size_t)i * OUT_C + c * 4);
    float4 bb = *reinterpret_cast<const float4*>(b2 + c * 4);
    o.x += xv.x * al + bb.x;
    o.y += xv.y * al + bb.y;
    o.z += xv.z * al + bb.z;
    o.w += xv.w * al + bb.w;
    *reinterpret_cast<float4*>(out + (size_t)i * OUT_C + c * 4) = o;
}

// ---------------- launch ----------------
extern "C" void kernel_launch(void* const* d_in, const int* in_sizes, int n_in,
                              void* d_out, int out_size) {
    const float* x        = (const float*)d_in[0];
    const int*   ei       = (const int*)d_in[1];
    const float* W1       = (const float*)d_in[2];
    const float* att_src1 = (const float*)d_in[3];
    const float* att_dst1 = (const float*)d_in[4];
    const float* b1       = (const float*)d_in[5];
    const float* W2       = (const float*)d_in[6];
    const float* att_src2 = (const float*)d_in[7];
    const float* att_dst2 = (const float*)d_in[8];
    const float* b2       = (const float*)d_in[9];
    float*       out      = (float*)d_out;

    // CRITICAL: get true DEVICE addresses of the __device__ scratch symbols.
    // Passing the symbol name from host code passes the host shadow address,
    // which GB300's ATS happily (and silently) dereferences into host memory.
    void *p_xh1 = nullptr, *p_acc1 = nullptr, *p_xh2 = nullptr;
    cudaGetSymbolAddress(&p_xh1,  g_xh1);
    cudaGetSymbolAddress(&p_acc1, g_acc1);
    cudaGetSymbolAddress(&p_xh2,  g_xh2);
    float* xh1  = (float*)p_xh1;
    float* acc1 = (float*)p_acc1;
    float* xh2  = (float*)p_xh2;

    const int T = 256;
    const int gemm_blocks  = (N_NODES + 63) / 64;
    const int node_warps   = (N_NODES * 32 + T - 1) / T;
    const int edge_threads = (N_EDGES + T - 1) / T;
    const int edge_warps   = (N_EDGES * 32 + T - 1) / T;

    // ---- canonicalize edge indices (dtype-agnostic) ----
    detect_kernel<<<1, T>>>((const unsigned int*)ei);
    convert_kernel<<<edge_threads, T>>>(ei);

    // ---- layer 1 ----
    zero_acc1_kernel<<<(N_NODES * 32 + T - 1) / T, T>>>();
    gemm_kernel<128, 8><<<gemm_blocks, T>>>(x, W1, xh1, N_NODES);
    attn1_kernel<<<node_warps, T>>>(att_src1, att_dst1);
    edge1_denom_kernel<<<edge_threads, T>>>();
    edge1_aggregate_kernel<<<edge_warps, T>>>();
    fin1_kernel<<<node_warps, T>>>(b1);

    // ---- layer 2 ----
    gemm_kernel<64, 4><<<gemm_blocks, T>>>(acc1, W2, xh2, N_NODES);
    attn2_kernel<<<node_warps, T>>>(att_src2, att_dst2);
    zero_out_kernel<<<(N_NODES * 16 + T - 1) / T, T>>>(out);
    edge2_denom_kernel<<<edge_threads, T>>>();
    edge2_aggregate_kernel<<<edge_warps, T>>>(out);
    fin2_kernel<<<(N_NODES * 16 + T - 1) / T, T>>>(b2, out);
}